// round 6
// baseline (speedup 1.0000x reference)
#include <cuda_runtime.h>
#include <cuda_bf16.h>
#include <cstdint>

#define SEQ 2048
#define DIM 1024
#define NHEAD 16
#define DHEAD 64
#define QKV_N (3 * DIM)   // 3072

// ---------------------------------------------------------------------------
// Scratch (device globals — allocation-free rule)
// ---------------------------------------------------------------------------
__device__ __nv_bfloat16 g_x_hi[SEQ * DIM];
__device__ __nv_bfloat16 g_x_lo[SEQ * DIM];
__device__ __nv_bfloat16 g_wqkv_hi[QKV_N * DIM];   // [N,K] transposed
__device__ __nv_bfloat16 g_wqkv_lo[QKV_N * DIM];
__device__ __nv_bfloat16 g_wout_hi[DIM * DIM];     // [N,K] transposed
__device__ __nv_bfloat16 g_wout_lo[DIM * DIM];
__device__ __nv_bfloat16 g_qkv_hi[SEQ * QKV_N];
__device__ __nv_bfloat16 g_qkv_lo[SEQ * QKV_N];
__device__ __nv_bfloat16 g_attn_hi[SEQ * DIM];
__device__ __nv_bfloat16 g_attn_lo[SEQ * DIM];

// ---------------------------------------------------------------------------
// PTX helpers (baseline sm_80+ features only: mma.sync / ldmatrix / cp.async)
// ---------------------------------------------------------------------------
__device__ __forceinline__ uint32_t smem_u32(const void* p) {
    uint32_t a;
    asm("{ .reg .u64 t; cvta.to.shared.u64 t, %1; cvt.u32.u64 %0, t; }"
        : "=r"(a) : "l"(p));
    return a;
}

__device__ __forceinline__ void ldsm_x4(uint32_t* r, uint32_t addr) {
    asm volatile("ldmatrix.sync.aligned.m8n8.x4.shared.b16 {%0,%1,%2,%3}, [%4];"
                 : "=r"(r[0]), "=r"(r[1]), "=r"(r[2]), "=r"(r[3]) : "r"(addr));
}

__device__ __forceinline__ void ldsm_x4_t(uint32_t* r, uint32_t addr) {
    asm volatile("ldmatrix.sync.aligned.m8n8.x4.trans.shared.b16 {%0,%1,%2,%3}, [%4];"
                 : "=r"(r[0]), "=r"(r[1]), "=r"(r[2]), "=r"(r[3]) : "r"(addr));
}

__device__ __forceinline__ void mma_bf16(float* d, const uint32_t* a,
                                         const uint32_t* b) {
    asm volatile(
        "mma.sync.aligned.m16n8k16.row.col.f32.bf16.bf16.f32 "
        "{%0,%1,%2,%3}, {%4,%5,%6,%7}, {%8,%9}, {%0,%1,%2,%3};"
        : "+f"(d[0]), "+f"(d[1]), "+f"(d[2]), "+f"(d[3])
        : "r"(a[0]), "r"(a[1]), "r"(a[2]), "r"(a[3]), "r"(b[0]), "r"(b[1]));
}

__device__ __forceinline__ void cp16(uint32_t dst, const void* src) {
    asm volatile("cp.async.cg.shared.global [%0], [%1], 16;"
                 :: "r"(dst), "l"(src));
}
#define CP_COMMIT() asm volatile("cp.async.commit_group;" ::: "memory")
#define CP_WAIT_1() asm volatile("cp.async.wait_group 1;" ::: "memory")

// swizzled smem byte offset for (row, 16B-seg) in a 128B-row tile
#define SWZ(r, seg) ((uint32_t)((r) * 128 + (((seg) ^ ((r) & 7)) << 4)))

// pack 2 floats into bf16x2 hi + residual bf16x2 lo
__device__ __forceinline__ void split_pack(float x, float y,
                                           uint32_t& hi, uint32_t& lo) {
    __nv_bfloat162 h = __floats2bfloat162_rn(x, y);
    float2 hf = __bfloat1622float2(h);
    __nv_bfloat162 l = __floats2bfloat162_rn(x - hf.x, y - hf.y);
    hi = *reinterpret_cast<uint32_t*>(&h);
    lo = *reinterpret_cast<uint32_t*>(&l);
}

// ---------------------------------------------------------------------------
// Elementwise split: fp32 -> bf16 hi + bf16 lo
// ---------------------------------------------------------------------------
__global__ __launch_bounds__(256) void split_kernel(
    const float* __restrict__ in,
    __nv_bfloat16* __restrict__ hi, __nv_bfloat16* __restrict__ lo)
{
    int i = (blockIdx.x * 256 + threadIdx.x) * 4;
    float4 v = *(const float4*)(in + i);
    uint32_t h0, l0, h1, l1;
    split_pack(v.x, v.y, h0, l0);
    split_pack(v.z, v.w, h1, l1);
    *(uint32_t*)(hi + i)     = h0;
    *(uint32_t*)(hi + i + 2) = h1;
    *(uint32_t*)(lo + i)     = l0;
    *(uint32_t*)(lo + i + 2) = l1;
}

// ---------------------------------------------------------------------------
// Transpose + split: W[K,N] fp32 -> Wt[N,K] bf16 hi/lo. 32x32 tiles.
// ---------------------------------------------------------------------------
__global__ __launch_bounds__(256) void tsplit_kernel(
    const float* __restrict__ W,
    __nv_bfloat16* __restrict__ hi, __nv_bfloat16* __restrict__ lo,
    int K, int N)
{
    __shared__ float t[32][33];
    const int n0 = blockIdx.x * 32, k0 = blockIdx.y * 32;
    const int tx = threadIdx.x, ty = threadIdx.y;   // 32 x 8

    #pragma unroll
    for (int j = 0; j < 4; j++)
        t[ty + 8 * j][tx] = W[(size_t)(k0 + ty + 8 * j) * N + n0 + tx];
    __syncthreads();

    #pragma unroll
    for (int j = 0; j < 4; j++) {
        int row = ty + 8 * j;
        float v = t[tx][row];
        __nv_bfloat16 h = __float2bfloat16(v);
        size_t o = (size_t)(n0 + row) * K + k0 + tx;
        hi[o] = h;
        lo[o] = __float2bfloat16(v - __bfloat162float(h));
    }
}

// ---------------------------------------------------------------------------
// Split-bf16 tensor-core GEMM via mma.sync (3 terms, fp32 accum).
// 2-stage cp.async software pipeline (2 x 64KB smem stages, 1 CTA/SM).
// Output either fp32 C (+bias) or bf16 hi/lo split (Chi/Clo non-null).
// ---------------------------------------------------------------------------
#define G_STAGE 65536
#define G_SMEM  (2 * G_STAGE)

__global__ __launch_bounds__(256, 1) void gemm_mma(
    const __nv_bfloat16* __restrict__ Ahi, const __nv_bfloat16* __restrict__ Alo,
    const __nv_bfloat16* __restrict__ Bhi, const __nv_bfloat16* __restrict__ Blo,
    float* __restrict__ C,
    __nv_bfloat16* __restrict__ Chi, __nv_bfloat16* __restrict__ Clo,
    int Mtot, int Ntot, int Ktot,
    const float* __restrict__ bias)
{
    extern __shared__ char smem[];
    const uint32_t sb = smem_u32(smem);
    const int tid  = threadIdx.x;
    const int wid  = tid >> 5;
    const int lane = tid & 31;
    const int row0 = blockIdx.y * 128, col0 = blockIdx.x * 128;

    const int m0 = (wid & 3) * 32;
    const int n0 = (wid >> 2) * 64;

    auto load_chunk = [&](int c, int stg) {
        const uint32_t base = sb + stg * G_STAGE;
        #pragma unroll
        for (int i = 0; i < 16; i++) {
            const int tile = i >> 2;
            int idx = tid + i * 256;
            int r   = (idx >> 3) & 127;
            int seg = idx & 7;
            const __nv_bfloat16* src;
            if (tile == 0)      src = Ahi + (size_t)(row0 + r) * Ktot;
            else if (tile == 1) src = Alo + (size_t)(row0 + r) * Ktot;
            else if (tile == 2) src = Bhi + (size_t)(col0 + r) * Ktot;
            else                src = Blo + (size_t)(col0 + r) * Ktot;
            cp16(base + tile * 16384 + SWZ(r, seg), src + c * 64 + seg * 8);
        }
    };

    float acc[2][8][4] = {};
    const int nchunks = Ktot >> 6;

    load_chunk(0, 0);
    CP_COMMIT();

    for (int c = 0; c < nchunks; c++) {
        if (c + 1 < nchunks) load_chunk(c + 1, (c + 1) & 1);
        CP_COMMIT();          // possibly-empty group keeps wait semantics uniform
        CP_WAIT_1();          // chunk c resident
        __syncthreads();

        const uint32_t st  = sb + (c & 1) * G_STAGE;
        const uint32_t sA  = st;
        const uint32_t sAL = st + 16384;
        const uint32_t sB  = st + 32768;
        const uint32_t sBL = st + 49152;

        #pragma unroll
        for (int ks = 0; ks < 4; ks++) {
            uint32_t aH[2][4], aL[2][4];
            #pragma unroll
            for (int mt = 0; mt < 2; mt++) {
                int r   = m0 + mt * 16 + (lane & 15);
                int seg = ks * 2 + (lane >> 4);
                uint32_t off = SWZ(r, seg);
                ldsm_x4(aH[mt], sA  + off);
                ldsm_x4(aL[mt], sAL + off);
            }
            #pragma unroll
            for (int np = 0; np < 4; np++) {
                int nr  = n0 + np * 16 + ((lane >> 4) << 3) + (lane & 7);
                int seg = ks * 2 + ((lane >> 3) & 1);
                uint32_t off = SWZ(nr, seg);
                uint32_t bH[4], bL[4];
                ldsm_x4(bH, sB  + off);
                ldsm_x4(bL, sBL + off);
                #pragma unroll
                for (int mt = 0; mt < 2; mt++) {
                    mma_bf16(acc[mt][np * 2],     aH[mt], bH);
                    mma_bf16(acc[mt][np * 2 + 1], aH[mt], bH + 2);
                    mma_bf16(acc[mt][np * 2],     aH[mt], bL);
                    mma_bf16(acc[mt][np * 2 + 1], aH[mt], bL + 2);
                    mma_bf16(acc[mt][np * 2],     aL[mt], bH);
                    mma_bf16(acc[mt][np * 2 + 1], aL[mt], bH + 2);
                }
            }
        }
        __syncthreads();   // protect stage (c&1) before it is reloaded at c+2
    }

    #pragma unroll
    for (int mt = 0; mt < 2; mt++) {
        int r = row0 + m0 + mt * 16 + (lane >> 2);
        #pragma unroll
        for (int nt = 0; nt < 8; nt++) {
            int cc = col0 + n0 + nt * 8 + (lane & 3) * 2;
            float bx = 0.f, by = 0.f;
            if (bias) { bx = bias[cc]; by = bias[cc + 1]; }
            float v0x = acc[mt][nt][0] + bx, v0y = acc[mt][nt][1] + by;
            float v1x = acc[mt][nt][2] + bx, v1y = acc[mt][nt][3] + by;
            if (Chi) {
                uint32_t h0, l0, h1, l1;
                split_pack(v0x, v0y, h0, l0);
                split_pack(v1x, v1y, h1, l1);
                *(uint32_t*)&Chi[(size_t)r * Ntot + cc]       = h0;
                *(uint32_t*)&Clo[(size_t)r * Ntot + cc]       = l0;
                *(uint32_t*)&Chi[(size_t)(r + 8) * Ntot + cc] = h1;
                *(uint32_t*)&Clo[(size_t)(r + 8) * Ntot + cc] = l1;
            } else {
                *(float2*)&C[(size_t)r * Ntot + cc]       = make_float2(v0x, v0y);
                *(float2*)&C[(size_t)(r + 8) * Ntot + cc] = make_float2(v1x, v1y);
            }
        }
    }
}

// ---------------------------------------------------------------------------
// Flash attention via mma.sync, split-bf16 (3 terms on QK^T and PV).
// CTA = 128 threads (4 warps), 64-query tile, 64-key steps.
// K/V double-buffered via cp.async pipeline. smem 80KB: Q (16K) + 2x32K KV.
// ---------------------------------------------------------------------------
#define AT_KV_STAGE 32768
#define AT_SMEM (16384 + 2 * AT_KV_STAGE)

__global__ __launch_bounds__(128, 2) void attn_mma(
    const __nv_bfloat16* __restrict__ qkv_hi,
    const __nv_bfloat16* __restrict__ qkv_lo,
    __nv_bfloat16* __restrict__ out_hi,
    __nv_bfloat16* __restrict__ out_lo)
{
    extern __shared__ char smem[];
    const uint32_t sb = smem_u32(smem);
    const uint32_t sQh = sb, sQl = sb + 8192;

    const int tid = threadIdx.x, wid = tid >> 5, lane = tid & 31;
    const int qb = blockIdx.x, h = blockIdx.y;
    const int q0 = qb * 64, hoff = h * DHEAD;

    auto load_kv = [&](int kt, int stg) {
        const uint32_t base = sb + 16384 + stg * AT_KV_STAGE;
        const int k0 = kt * 64;
        #pragma unroll
        for (int i = 0; i < 4; i++) {
            int idx = tid + i * 128;
            int r = idx >> 3, seg = idx & 7;
            size_t g = (size_t)(k0 + r) * QKV_N + DIM + hoff + seg * 8;
            uint32_t off = SWZ(r, seg);
            cp16(base + off,         qkv_hi + g);
            cp16(base + 8192 + off,  qkv_lo + g);
            cp16(base + 16384 + off, qkv_hi + g + DIM);
            cp16(base + 24576 + off, qkv_lo + g + DIM);
        }
    };

    // group 0: Q tiles + KV step 0
    #pragma unroll
    for (int i = 0; i < 4; i++) {
        int idx = tid + i * 128;
        int r = idx >> 3, seg = idx & 7;
        size_t g = (size_t)(q0 + r) * QKV_N + hoff + seg * 8;
        cp16(sQh + SWZ(r, seg), qkv_hi + g);
        cp16(sQl + SWZ(r, seg), qkv_lo + g);
    }
    load_kv(0, 0);
    CP_COMMIT();

    float o[8][4] = {};
    float m_i[2] = {-1e30f, -1e30f};
    float l_i[2] = {0.f, 0.f};

    const int rA = q0 + wid * 16 + (lane >> 2);

    for (int kt = 0; kt <= qb; kt++) {
        const int k0 = kt * 64;

        if (kt + 1 <= qb) load_kv(kt + 1, (kt + 1) & 1);
        CP_COMMIT();
        CP_WAIT_1();
        __syncthreads();

        const uint32_t kvb = sb + 16384 + (kt & 1) * AT_KV_STAGE;
        const uint32_t sKh = kvb,          sKl = kvb + 8192;
        const uint32_t sVh = kvb + 16384,  sVl = kvb + 24576;

        // ---- S = Q K^T (3-term split) ----
        float s[8][4] = {};
        #pragma unroll
        for (int ks = 0; ks < 4; ks++) {
            uint32_t aH[4], aL[4];
            {
                int r   = wid * 16 + (lane & 15);
                int seg = ks * 2 + (lane >> 4);
                ldsm_x4(aH, sQh + SWZ(r, seg));
                ldsm_x4(aL, sQl + SWZ(r, seg));
            }
            #pragma unroll
            for (int np = 0; np < 4; np++) {
                int nr = np * 16 + ((lane >> 4) << 3) + (lane & 7);
                int sg = ks * 2 + ((lane >> 3) & 1);
                uint32_t off = SWZ(nr, sg);
                uint32_t bH[4], bL[4];
                ldsm_x4(bH, sKh + off);
                ldsm_x4(bL, sKl + off);
                mma_bf16(s[np * 2],     aH, bH);
                mma_bf16(s[np * 2 + 1], aH, bH + 2);
                mma_bf16(s[np * 2],     aH, bL);
                mma_bf16(s[np * 2 + 1], aH, bL + 2);
                mma_bf16(s[np * 2],     aL, bH);
                mma_bf16(s[np * 2 + 1], aL, bH + 2);
            }
        }

        // ---- scale + causal mask ----
        #pragma unroll
        for (int j = 0; j < 8; j++) {
            s[j][0] *= 0.125f; s[j][1] *= 0.125f;
            s[j][2] *= 0.125f; s[j][3] *= 0.125f;
        }
        if (kt == qb) {
            #pragma unroll
            for (int j = 0; j < 8; j++) {
                int col = k0 + j * 8 + (lane & 3) * 2;
                if (col > rA)         s[j][0] = -1e30f;
                if (col + 1 > rA)     s[j][1] = -1e30f;
                if (col > rA + 8)     s[j][2] = -1e30f;
                if (col + 1 > rA + 8) s[j][3] = -1e30f;
            }
        }

        // ---- online softmax on register fragments ----
        float mxA = -1e30f, mxB = -1e30f;
        #pragma unroll
        for (int j = 0; j < 8; j++) {
            mxA = fmaxf(mxA, fmaxf(s[j][0], s[j][1]));
            mxB = fmaxf(mxB, fmaxf(s[j][2], s[j][3]));
        }
        mxA = fmaxf(mxA, __shfl_xor_sync(0xffffffffu, mxA, 1));
        mxA = fmaxf(mxA, __shfl_xor_sync(0xffffffffu, mxA, 2));
        mxB = fmaxf(mxB, __shfl_xor_sync(0xffffffffu, mxB, 1));
        mxB = fmaxf(mxB, __shfl_xor_sync(0xffffffffu, mxB, 2));

        float mA = fmaxf(m_i[0], mxA), mB = fmaxf(m_i[1], mxB);
        float scA = __expf(m_i[0] - mA), scB = __expf(m_i[1] - mB);
        float lA = 0.f, lB = 0.f;
        #pragma unroll
        for (int j = 0; j < 8; j++) {
            s[j][0] = __expf(s[j][0] - mA);
            s[j][1] = __expf(s[j][1] - mA);
            s[j][2] = __expf(s[j][2] - mB);
            s[j][3] = __expf(s[j][3] - mB);
            lA += s[j][0] + s[j][1];
            lB += s[j][2] + s[j][3];
        }
        lA += __shfl_xor_sync(0xffffffffu, lA, 1);
        lA += __shfl_xor_sync(0xffffffffu, lA, 2);
        lB += __shfl_xor_sync(0xffffffffu, lB, 1);
        lB += __shfl_xor_sync(0xffffffffu, lB, 2);
        l_i[0] = l_i[0] * scA + lA;  m_i[0] = mA;
        l_i[1] = l_i[1] * scB + lB;  m_i[1] = mB;
        #pragma unroll
        for (int j = 0; j < 8; j++) {
            o[j][0] *= scA; o[j][1] *= scA;
            o[j][2] *= scB; o[j][3] *= scB;
        }

        // ---- O += P V (3-term split; P packed from C-frags, V via ldsm.trans) ----
        #pragma unroll
        for (int t = 0; t < 4; t++) {
            uint32_t pH[4], pL[4];
            split_pack(s[2 * t][0],     s[2 * t][1],     pH[0], pL[0]);
            split_pack(s[2 * t][2],     s[2 * t][3],     pH[1], pL[1]);
            split_pack(s[2 * t + 1][0], s[2 * t + 1][1], pH[2], pL[2]);
            split_pack(s[2 * t + 1][2], s[2 * t + 1][3], pH[3], pL[3]);
            #pragma unroll
            for (int sp = 0; sp < 4; sp++) {
                int g  = lane >> 3, rr = lane & 7;
                uint32_t off = SWZ(t * 16 + rr + ((g & 1) << 3),
                                   sp * 2 + (g >> 1));
                uint32_t bH[4], bL[4];
                ldsm_x4_t(bH, sVh + off);
                ldsm_x4_t(bL, sVl + off);
                mma_bf16(o[sp * 2],     pH, bH);
                mma_bf16(o[sp * 2 + 1], pH, bH + 2);
                mma_bf16(o[sp * 2],     pH, bL);
                mma_bf16(o[sp * 2 + 1], pH, bL + 2);
                mma_bf16(o[sp * 2],     pL, bH);
                mma_bf16(o[sp * 2 + 1], pL, bH + 2);
            }
        }
        __syncthreads();   // protect KV stage (kt&1) before reload at kt+2
    }

    // ---- epilogue: normalize, write split bf16 ----
    float invA = 1.0f / l_i[0], invB = 1.0f / l_i[1];
    #pragma unroll
    for (int j = 0; j < 8; j++) {
        int d = hoff + j * 8 + (lane & 3) * 2;
        uint32_t hA, lA2, hB, lB2;
        split_pack(o[j][0] * invA, o[j][1] * invA, hA, lA2);
        split_pack(o[j][2] * invB, o[j][3] * invB, hB, lB2);
        *(uint32_t*)&out_hi[(size_t)rA * DIM + d]       = hA;
        *(uint32_t*)&out_lo[(size_t)rA * DIM + d]       = lA2;
        *(uint32_t*)&out_hi[(size_t)(rA + 8) * DIM + d] = hB;
        *(uint32_t*)&out_lo[(size_t)(rA + 8) * DIM + d] = lB2;
    }
}

// ---------------------------------------------------------------------------
extern "C" void kernel_launch(void* const* d_in, const int* in_sizes, int n_in,
                              void* d_out, int out_size)
{
    const float* x    = (const float*)d_in[0];
    const float* Wqkv = (const float*)d_in[1];
    const float* Wout = (const float*)d_in[2];
    const float* bias = (const float*)d_in[3];
    float* out = (float*)d_out;

    __nv_bfloat16 *xh, *xl, *wqh, *wql, *woh, *wol, *qh, *ql, *ah, *al;
    cudaGetSymbolAddress((void**)&xh,  g_x_hi);
    cudaGetSymbolAddress((void**)&xl,  g_x_lo);
    cudaGetSymbolAddress((void**)&wqh, g_wqkv_hi);
    cudaGetSymbolAddress((void**)&wql, g_wqkv_lo);
    cudaGetSymbolAddress((void**)&woh, g_wout_hi);
    cudaGetSymbolAddress((void**)&wol, g_wout_lo);
    cudaGetSymbolAddress((void**)&qh,  g_qkv_hi);
    cudaGetSymbolAddress((void**)&ql,  g_qkv_lo);
    cudaGetSymbolAddress((void**)&ah,  g_attn_hi);
    cudaGetSymbolAddress((void**)&al,  g_attn_lo);

    cudaFuncSetAttribute(gemm_mma, cudaFuncAttributeMaxDynamicSharedMemorySize,
                         G_SMEM);
    cudaFuncSetAttribute(attn_mma, cudaFuncAttributeMaxDynamicSharedMemorySize,
                         AT_SMEM);

    // Prep: split x, transpose+split weights
    split_kernel<<<SEQ * DIM / 1024, 256>>>(x, xh, xl);
    tsplit_kernel<<<dim3(QKV_N / 32, DIM / 32), dim3(32, 8)>>>(Wqkv, wqh, wql,
                                                               DIM, QKV_N);
    tsplit_kernel<<<dim3(DIM / 32, DIM / 32), dim3(32, 8)>>>(Wout, woh, wol,
                                                             DIM, DIM);

    // 1) qkv = x @ Wqkv  -> bf16 hi/lo directly
    gemm_mma<<<dim3(QKV_N / 128, SEQ / 128), 256, G_SMEM>>>(
        xh, xl, wqh, wql, nullptr, qh, ql, SEQ, QKV_N, DIM, nullptr);

    // 2) attention -> bf16 hi/lo directly
    attn_mma<<<dim3(SEQ / 64, NHEAD), 128, AT_SMEM>>>(qh, ql, ah, al);

    // 3) out = attn @ Wout + bias  (fp32 output)
    gemm_mma<<<dim3(DIM / 128, SEQ / 128), 256, G_SMEM>>>(
        ah, al, woh, wol, out, nullptr, nullptr, SEQ, DIM, DIM, bias);
}

// round 7
// speedup vs baseline: 1.4365x; 1.4365x over previous
#include <cuda_runtime.h>
#include <cuda_bf16.h>
#include <cstdint>

#define SEQ 2048
#define DIM 1024
#define NHEAD 16
#define DHEAD 64
#define QKV_N (3 * DIM)   // 3072

// ---------------------------------------------------------------------------
// Scratch (device globals — allocation-free rule)
// ---------------------------------------------------------------------------
__device__ __nv_bfloat16 g_x_hi[SEQ * DIM];
__device__ __nv_bfloat16 g_x_lo[SEQ * DIM];
__device__ __nv_bfloat16 g_wqkv_hi[QKV_N * DIM];   // [N,K] transposed
__device__ __nv_bfloat16 g_wqkv_lo[QKV_N * DIM];
__device__ __nv_bfloat16 g_wout_hi[DIM * DIM];     // [N,K] transposed
__device__ __nv_bfloat16 g_wout_lo[DIM * DIM];
__device__ __nv_bfloat16 g_qkv_hi[SEQ * QKV_N];
__device__ __nv_bfloat16 g_qkv_lo[SEQ * QKV_N];
__device__ __nv_bfloat16 g_attn_hi[SEQ * DIM];
__device__ __nv_bfloat16 g_attn_lo[SEQ * DIM];

// ---------------------------------------------------------------------------
// PTX helpers (baseline sm_80+ features only: mma.sync / ldmatrix / cp.async)
// ---------------------------------------------------------------------------
__device__ __forceinline__ uint32_t smem_u32(const void* p) {
    uint32_t a;
    asm("{ .reg .u64 t; cvta.to.shared.u64 t, %1; cvt.u32.u64 %0, t; }"
        : "=r"(a) : "l"(p));
    return a;
}

__device__ __forceinline__ void ldsm_x4(uint32_t* r, uint32_t addr) {
    asm volatile("ldmatrix.sync.aligned.m8n8.x4.shared.b16 {%0,%1,%2,%3}, [%4];"
                 : "=r"(r[0]), "=r"(r[1]), "=r"(r[2]), "=r"(r[3]) : "r"(addr));
}

__device__ __forceinline__ void ldsm_x4_t(uint32_t* r, uint32_t addr) {
    asm volatile("ldmatrix.sync.aligned.m8n8.x4.trans.shared.b16 {%0,%1,%2,%3}, [%4];"
                 : "=r"(r[0]), "=r"(r[1]), "=r"(r[2]), "=r"(r[3]) : "r"(addr));
}

__device__ __forceinline__ void mma_bf16(float* d, const uint32_t* a,
                                         const uint32_t* b) {
    asm volatile(
        "mma.sync.aligned.m16n8k16.row.col.f32.bf16.bf16.f32 "
        "{%0,%1,%2,%3}, {%4,%5,%6,%7}, {%8,%9}, {%0,%1,%2,%3};"
        : "+f"(d[0]), "+f"(d[1]), "+f"(d[2]), "+f"(d[3])
        : "r"(a[0]), "r"(a[1]), "r"(a[2]), "r"(a[3]), "r"(b[0]), "r"(b[1]));
}

__device__ __forceinline__ void cp16(uint32_t dst, const void* src) {
    asm volatile("cp.async.cg.shared.global [%0], [%1], 16;"
                 :: "r"(dst), "l"(src));
}
#define CP_COMMIT()   asm volatile("cp.async.commit_group;" ::: "memory")
#define CP_WAIT_1()   asm volatile("cp.async.wait_group 1;" ::: "memory")
#define CP_WAIT_ALL() asm volatile("cp.async.wait_all;" ::: "memory")

// swizzled smem byte offset for (row, 16B-seg), 128B rows (8 segs)
#define SWZ(r, seg) ((uint32_t)((r) * 128 + (((seg) ^ ((r) & 7)) << 4)))
// swizzled smem byte offset for (row, 16B-seg), 64B rows (4 segs)
#define SWZ32(r, seg) ((uint32_t)((r) * 64 + (((seg) ^ (((r) >> 1) & 3)) << 4)))

// pack 2 floats into bf16x2 hi + residual bf16x2 lo
__device__ __forceinline__ void split_pack(float x, float y,
                                           uint32_t& hi, uint32_t& lo) {
    __nv_bfloat162 h = __floats2bfloat162_rn(x, y);
    float2 hf = __bfloat1622float2(h);
    __nv_bfloat162 l = __floats2bfloat162_rn(x - hf.x, y - hf.y);
    hi = *reinterpret_cast<uint32_t*>(&h);
    lo = *reinterpret_cast<uint32_t*>(&l);
}

// ---------------------------------------------------------------------------
// Elementwise split: fp32 -> bf16 hi + bf16 lo
// ---------------------------------------------------------------------------
__global__ __launch_bounds__(256) void split_kernel(
    const float* __restrict__ in,
    __nv_bfloat16* __restrict__ hi, __nv_bfloat16* __restrict__ lo)
{
    int i = (blockIdx.x * 256 + threadIdx.x) * 4;
    float4 v = *(const float4*)(in + i);
    uint32_t h0, l0, h1, l1;
    split_pack(v.x, v.y, h0, l0);
    split_pack(v.z, v.w, h1, l1);
    *(uint32_t*)(hi + i)     = h0;
    *(uint32_t*)(hi + i + 2) = h1;
    *(uint32_t*)(lo + i)     = l0;
    *(uint32_t*)(lo + i + 2) = l1;
}

// ---------------------------------------------------------------------------
// Transpose + split: W[K,N] fp32 -> Wt[N,K] bf16 hi/lo. 32x32 tiles.
// ---------------------------------------------------------------------------
__global__ __launch_bounds__(256) void tsplit_kernel(
    const float* __restrict__ W,
    __nv_bfloat16* __restrict__ hi, __nv_bfloat16* __restrict__ lo,
    int K, int N)
{
    __shared__ float t[32][33];
    const int n0 = blockIdx.x * 32, k0 = blockIdx.y * 32;
    const int tx = threadIdx.x, ty = threadIdx.y;   // 32 x 8

    #pragma unroll
    for (int j = 0; j < 4; j++)
        t[ty + 8 * j][tx] = W[(size_t)(k0 + ty + 8 * j) * N + n0 + tx];
    __syncthreads();

    #pragma unroll
    for (int j = 0; j < 4; j++) {
        int row = ty + 8 * j;
        float v = t[tx][row];
        __nv_bfloat16 h = __float2bfloat16(v);
        size_t o = (size_t)(n0 + row) * K + k0 + tx;
        hi[o] = h;
        lo[o] = __float2bfloat16(v - __bfloat162float(h));
    }
}

// ---------------------------------------------------------------------------
// Split-bf16 tensor-core GEMM via mma.sync (3 terms, fp32 accum).
// BK=32 chunks, 2-stage cp.async pipeline: 2 x 32KB stages = 64KB total,
// __launch_bounds__(256,2) keeps regs<=128 -> 2 CTAs/SM (cross-CTA overlap
// preserved AND intra-CTA prefetch added).
// ---------------------------------------------------------------------------
#define G_STAGE 32768
#define G_SMEM  (2 * G_STAGE)

__global__ __launch_bounds__(256, 2) void gemm_mma(
    const __nv_bfloat16* __restrict__ Ahi, const __nv_bfloat16* __restrict__ Alo,
    const __nv_bfloat16* __restrict__ Bhi, const __nv_bfloat16* __restrict__ Blo,
    float* __restrict__ C,
    __nv_bfloat16* __restrict__ Chi, __nv_bfloat16* __restrict__ Clo,
    int Mtot, int Ntot, int Ktot,
    const float* __restrict__ bias)
{
    extern __shared__ char smem[];
    const uint32_t sb = smem_u32(smem);
    const int tid  = threadIdx.x;
    const int wid  = tid >> 5;
    const int lane = tid & 31;
    const int row0 = blockIdx.y * 128, col0 = blockIdx.x * 128;

    const int m0 = (wid & 3) * 32;
    const int n0 = (wid >> 2) * 64;

    // load K-chunk c (32 wide) into stage stg: 4 tiles x 128 rows x 64B
    auto load_chunk = [&](int c, int stg) {
        const uint32_t base = sb + stg * G_STAGE;
        #pragma unroll
        for (int i = 0; i < 8; i++) {
            const int tile = i >> 1;               // compile-time
            int idx = tid + i * 256;
            int r   = (idx >> 2) & 127;
            int seg = idx & 3;
            const __nv_bfloat16* src;
            if (tile == 0)      src = Ahi + (size_t)(row0 + r) * Ktot;
            else if (tile == 1) src = Alo + (size_t)(row0 + r) * Ktot;
            else if (tile == 2) src = Bhi + (size_t)(col0 + r) * Ktot;
            else                src = Blo + (size_t)(col0 + r) * Ktot;
            cp16(base + tile * 8192 + SWZ32(r, seg), src + c * 32 + seg * 8);
        }
    };

    float acc[2][8][4] = {};
    const int nchunks = Ktot >> 5;

    load_chunk(0, 0);
    CP_COMMIT();

    for (int c = 0; c < nchunks; c++) {
        if (c + 1 < nchunks) load_chunk(c + 1, (c + 1) & 1);
        CP_COMMIT();          // possibly-empty group keeps wait count uniform
        CP_WAIT_1();          // chunk c resident
        __syncthreads();

        const uint32_t st  = sb + (c & 1) * G_STAGE;
        const uint32_t sA  = st;
        const uint32_t sAL = st + 8192;
        const uint32_t sB  = st + 16384;
        const uint32_t sBL = st + 24576;

        #pragma unroll
        for (int ks = 0; ks < 2; ks++) {
            uint32_t aH[2][4], aL[2][4];
            #pragma unroll
            for (int mt = 0; mt < 2; mt++) {
                int r   = m0 + mt * 16 + (lane & 15);
                int seg = ks * 2 + (lane >> 4);
                uint32_t off = SWZ32(r, seg);
                ldsm_x4(aH[mt], sA  + off);
                ldsm_x4(aL[mt], sAL + off);
            }
            #pragma unroll
            for (int np = 0; np < 4; np++) {
                int nr  = n0 + np * 16 + ((lane >> 4) << 3) + (lane & 7);
                int seg = ks * 2 + ((lane >> 3) & 1);
                uint32_t off = SWZ32(nr, seg);
                uint32_t bH[4], bL[4];
                ldsm_x4(bH, sB  + off);
                ldsm_x4(bL, sBL + off);
                #pragma unroll
                for (int mt = 0; mt < 2; mt++) {
                    mma_bf16(acc[mt][np * 2],     aH[mt], bH);
                    mma_bf16(acc[mt][np * 2 + 1], aH[mt], bH + 2);
                    mma_bf16(acc[mt][np * 2],     aH[mt], bL);
                    mma_bf16(acc[mt][np * 2 + 1], aH[mt], bL + 2);
                    mma_bf16(acc[mt][np * 2],     aL[mt], bH);
                    mma_bf16(acc[mt][np * 2 + 1], aL[mt], bH + 2);
                }
            }
        }
        __syncthreads();   // protect stage (c&1) before reload at c+2
    }

    #pragma unroll
    for (int mt = 0; mt < 2; mt++) {
        int r = row0 + m0 + mt * 16 + (lane >> 2);
        #pragma unroll
        for (int nt = 0; nt < 8; nt++) {
            int cc = col0 + n0 + nt * 8 + (lane & 3) * 2;
            float bx = 0.f, by = 0.f;
            if (bias) { bx = bias[cc]; by = bias[cc + 1]; }
            float v0x = acc[mt][nt][0] + bx, v0y = acc[mt][nt][1] + by;
            float v1x = acc[mt][nt][2] + bx, v1y = acc[mt][nt][3] + by;
            if (Chi) {
                uint32_t h0, l0, h1, l1;
                split_pack(v0x, v0y, h0, l0);
                split_pack(v1x, v1y, h1, l1);
                *(uint32_t*)&Chi[(size_t)r * Ntot + cc]       = h0;
                *(uint32_t*)&Clo[(size_t)r * Ntot + cc]       = l0;
                *(uint32_t*)&Chi[(size_t)(r + 8) * Ntot + cc] = h1;
                *(uint32_t*)&Clo[(size_t)(r + 8) * Ntot + cc] = l1;
            } else {
                *(float2*)&C[(size_t)r * Ntot + cc]       = make_float2(v0x, v0y);
                *(float2*)&C[(size_t)(r + 8) * Ntot + cc] = make_float2(v1x, v1y);
            }
        }
    }
}

// ---------------------------------------------------------------------------
// Flash attention via mma.sync, split-bf16 (3 terms on QK^T and PV).
// R5 version (known good): 128 threads, 64x64 tiles, single KV buffer,
// 48KB smem, 3 CTAs/SM.
// ---------------------------------------------------------------------------
#define AT_SMEM 49152

__global__ __launch_bounds__(128, 3) void attn_mma(
    const __nv_bfloat16* __restrict__ qkv_hi,
    const __nv_bfloat16* __restrict__ qkv_lo,
    __nv_bfloat16* __restrict__ out_hi,
    __nv_bfloat16* __restrict__ out_lo)
{
    extern __shared__ char smem[];
    const uint32_t sb = smem_u32(smem);
    const uint32_t sQh = sb,         sQl = sb + 8192;
    const uint32_t sKh = sb + 16384, sKl = sb + 24576;
    const uint32_t sVh = sb + 32768, sVl = sb + 40960;

    const int tid = threadIdx.x, wid = tid >> 5, lane = tid & 31;
    const int qb = blockIdx.x, h = blockIdx.y;
    const int q0 = qb * 64, hoff = h * DHEAD;

    #pragma unroll
    for (int i = 0; i < 4; i++) {
        int idx = tid + i * 128;
        int r = idx >> 3, seg = idx & 7;
        size_t g = (size_t)(q0 + r) * QKV_N + hoff + seg * 8;
        cp16(sQh + SWZ(r, seg), qkv_hi + g);
        cp16(sQl + SWZ(r, seg), qkv_lo + g);
    }

    float o[8][4] = {};
    float m_i[2] = {-1e30f, -1e30f};
    float l_i[2] = {0.f, 0.f};

    const int rA = q0 + wid * 16 + (lane >> 2);

    for (int kt = 0; kt <= qb; kt++) {
        const int k0 = kt * 64;

        #pragma unroll
        for (int i = 0; i < 4; i++) {
            int idx = tid + i * 128;
            int r = idx >> 3, seg = idx & 7;
            size_t g = (size_t)(k0 + r) * QKV_N + DIM + hoff + seg * 8;
            cp16(sKh + SWZ(r, seg), qkv_hi + g);
            cp16(sKl + SWZ(r, seg), qkv_lo + g);
            cp16(sVh + SWZ(r, seg), qkv_hi + g + DIM);
            cp16(sVl + SWZ(r, seg), qkv_lo + g + DIM);
        }
        CP_WAIT_ALL();
        __syncthreads();

        // ---- S = Q K^T (3-term split) ----
        float s[8][4] = {};
        #pragma unroll
        for (int ks = 0; ks < 4; ks++) {
            uint32_t aH[4], aL[4];
            {
                int r   = wid * 16 + (lane & 15);
                int seg = ks * 2 + (lane >> 4);
                ldsm_x4(aH, sQh + SWZ(r, seg));
                ldsm_x4(aL, sQl + SWZ(r, seg));
            }
            #pragma unroll
            for (int np = 0; np < 4; np++) {
                int nr = np * 16 + ((lane >> 4) << 3) + (lane & 7);
                int sg = ks * 2 + ((lane >> 3) & 1);
                uint32_t off = SWZ(nr, sg);
                uint32_t bH[4], bL[4];
                ldsm_x4(bH, sKh + off);
                ldsm_x4(bL, sKl + off);
                mma_bf16(s[np * 2],     aH, bH);
                mma_bf16(s[np * 2 + 1], aH, bH + 2);
                mma_bf16(s[np * 2],     aH, bL);
                mma_bf16(s[np * 2 + 1], aH, bL + 2);
                mma_bf16(s[np * 2],     aL, bH);
                mma_bf16(s[np * 2 + 1], aL, bH + 2);
            }
        }

        // ---- scale + causal mask ----
        #pragma unroll
        for (int j = 0; j < 8; j++) {
            s[j][0] *= 0.125f; s[j][1] *= 0.125f;
            s[j][2] *= 0.125f; s[j][3] *= 0.125f;
        }
        if (kt == qb) {
            #pragma unroll
            for (int j = 0; j < 8; j++) {
                int col = k0 + j * 8 + (lane & 3) * 2;
                if (col > rA)         s[j][0] = -1e30f;
                if (col + 1 > rA)     s[j][1] = -1e30f;
                if (col > rA + 8)     s[j][2] = -1e30f;
                if (col + 1 > rA + 8) s[j][3] = -1e30f;
            }
        }

        // ---- online softmax on register fragments ----
        float mxA = -1e30f, mxB = -1e30f;
        #pragma unroll
        for (int j = 0; j < 8; j++) {
            mxA = fmaxf(mxA, fmaxf(s[j][0], s[j][1]));
            mxB = fmaxf(mxB, fmaxf(s[j][2], s[j][3]));
        }
        mxA = fmaxf(mxA, __shfl_xor_sync(0xffffffffu, mxA, 1));
        mxA = fmaxf(mxA, __shfl_xor_sync(0xffffffffu, mxA, 2));
        mxB = fmaxf(mxB, __shfl_xor_sync(0xffffffffu, mxB, 1));
        mxB = fmaxf(mxB, __shfl_xor_sync(0xffffffffu, mxB, 2));

        float mA = fmaxf(m_i[0], mxA), mB = fmaxf(m_i[1], mxB);
        float scA = __expf(m_i[0] - mA), scB = __expf(m_i[1] - mB);
        float lA = 0.f, lB = 0.f;
        #pragma unroll
        for (int j = 0; j < 8; j++) {
            s[j][0] = __expf(s[j][0] - mA);
            s[j][1] = __expf(s[j][1] - mA);
            s[j][2] = __expf(s[j][2] - mB);
            s[j][3] = __expf(s[j][3] - mB);
            lA += s[j][0] + s[j][1];
            lB += s[j][2] + s[j][3];
        }
        lA += __shfl_xor_sync(0xffffffffu, lA, 1);
        lA += __shfl_xor_sync(0xffffffffu, lA, 2);
        lB += __shfl_xor_sync(0xffffffffu, lB, 1);
        lB += __shfl_xor_sync(0xffffffffu, lB, 2);
        l_i[0] = l_i[0] * scA + lA;  m_i[0] = mA;
        l_i[1] = l_i[1] * scB + lB;  m_i[1] = mB;
        #pragma unroll
        for (int j = 0; j < 8; j++) {
            o[j][0] *= scA; o[j][1] *= scA;
            o[j][2] *= scB; o[j][3] *= scB;
        }

        // ---- O += P V (3-term split; P packed from C-frags, V via ldsm.trans) ----
        #pragma unroll
        for (int t = 0; t < 4; t++) {
            uint32_t pH[4], pL[4];
            split_pack(s[2 * t][0],     s[2 * t][1],     pH[0], pL[0]);
            split_pack(s[2 * t][2],     s[2 * t][3],     pH[1], pL[1]);
            split_pack(s[2 * t + 1][0], s[2 * t + 1][1], pH[2], pL[2]);
            split_pack(s[2 * t + 1][2], s[2 * t + 1][3], pH[3], pL[3]);
            #pragma unroll
            for (int sp = 0; sp < 4; sp++) {
                int g  = lane >> 3, rr = lane & 7;
                uint32_t off = SWZ(t * 16 + rr + ((g & 1) << 3),
                                   sp * 2 + (g >> 1));
                uint32_t bH[4], bL[4];
                ldsm_x4_t(bH, sVh + off);
                ldsm_x4_t(bL, sVl + off);
                mma_bf16(o[sp * 2],     pH, bH);
                mma_bf16(o[sp * 2 + 1], pH, bH + 2);
                mma_bf16(o[sp * 2],     pH, bL);
                mma_bf16(o[sp * 2 + 1], pH, bL + 2);
                mma_bf16(o[sp * 2],     pL, bH);
                mma_bf16(o[sp * 2 + 1], pL, bH + 2);
            }
        }
        __syncthreads();
    }

    // ---- epilogue: normalize, write split bf16 ----
    float invA = 1.0f / l_i[0], invB = 1.0f / l_i[1];
    #pragma unroll
    for (int j = 0; j < 8; j++) {
        int d = hoff + j * 8 + (lane & 3) * 2;
        uint32_t hA, lA2, hB, lB2;
        split_pack(o[j][0] * invA, o[j][1] * invA, hA, lA2);
        split_pack(o[j][2] * invB, o[j][3] * invB, hB, lB2);
        *(uint32_t*)&out_hi[(size_t)rA * DIM + d]       = hA;
        *(uint32_t*)&out_lo[(size_t)rA * DIM + d]       = lA2;
        *(uint32_t*)&out_hi[(size_t)(rA + 8) * DIM + d] = hB;
        *(uint32_t*)&out_lo[(size_t)(rA + 8) * DIM + d] = lB2;
    }
}

// ---------------------------------------------------------------------------
extern "C" void kernel_launch(void* const* d_in, const int* in_sizes, int n_in,
                              void* d_out, int out_size)
{
    const float* x    = (const float*)d_in[0];
    const float* Wqkv = (const float*)d_in[1];
    const float* Wout = (const float*)d_in[2];
    const float* bias = (const float*)d_in[3];
    float* out = (float*)d_out;

    __nv_bfloat16 *xh, *xl, *wqh, *wql, *woh, *wol, *qh, *ql, *ah, *al;
    cudaGetSymbolAddress((void**)&xh,  g_x_hi);
    cudaGetSymbolAddress((void**)&xl,  g_x_lo);
    cudaGetSymbolAddress((void**)&wqh, g_wqkv_hi);
    cudaGetSymbolAddress((void**)&wql, g_wqkv_lo);
    cudaGetSymbolAddress((void**)&woh, g_wout_hi);
    cudaGetSymbolAddress((void**)&wol, g_wout_lo);
    cudaGetSymbolAddress((void**)&qh,  g_qkv_hi);
    cudaGetSymbolAddress((void**)&ql,  g_qkv_lo);
    cudaGetSymbolAddress((void**)&ah,  g_attn_hi);
    cudaGetSymbolAddress((void**)&al,  g_attn_lo);

    cudaFuncSetAttribute(gemm_mma, cudaFuncAttributeMaxDynamicSharedMemorySize,
                         G_SMEM);
    cudaFuncSetAttribute(attn_mma, cudaFuncAttributeMaxDynamicSharedMemorySize,
                         AT_SMEM);

    // Prep: split x, transpose+split weights
    split_kernel<<<SEQ * DIM / 1024, 256>>>(x, xh, xl);
    tsplit_kernel<<<dim3(QKV_N / 32, DIM / 32), dim3(32, 8)>>>(Wqkv, wqh, wql,
                                                               DIM, QKV_N);
    tsplit_kernel<<<dim3(DIM / 32, DIM / 32), dim3(32, 8)>>>(Wout, woh, wol,
                                                             DIM, DIM);

    // 1) qkv = x @ Wqkv  -> bf16 hi/lo directly
    gemm_mma<<<dim3(QKV_N / 128, SEQ / 128), 256, G_SMEM>>>(
        xh, xl, wqh, wql, nullptr, qh, ql, SEQ, QKV_N, DIM, nullptr);

    // 2) attention -> bf16 hi/lo directly
    attn_mma<<<dim3(SEQ / 64, NHEAD), 128, AT_SMEM>>>(qh, ql, ah, al);

    // 3) out = attn @ Wout + bias  (fp32 output)
    gemm_mma<<<dim3(DIM / 128, SEQ / 128), 256, G_SMEM>>>(
        ah, al, woh, wol, out, nullptr, nullptr, SEQ, DIM, DIM, bias);
}

// round 8
// speedup vs baseline: 1.5383x; 1.0708x over previous
#include <cuda_runtime.h>
#include <cuda_bf16.h>
#include <cstdint>

#define SEQ 2048
#define DIM 1024
#define NHEAD 16
#define DHEAD 64
#define QKV_N (3 * DIM)   // 3072
#define NTILES (SEQ / 64) // 32

// ---------------------------------------------------------------------------
// Scratch (device globals — allocation-free rule)
// ---------------------------------------------------------------------------
__device__ __nv_bfloat16 g_x_hi[SEQ * DIM];
__device__ __nv_bfloat16 g_x_lo[SEQ * DIM];
__device__ __nv_bfloat16 g_wqkv_hi[QKV_N * DIM];   // [N,K] transposed
__device__ __nv_bfloat16 g_wqkv_lo[QKV_N * DIM];
__device__ __nv_bfloat16 g_wout_hi[DIM * DIM];     // [N,K] transposed
__device__ __nv_bfloat16 g_wout_lo[DIM * DIM];
__device__ __nv_bfloat16 g_qkv_hi[SEQ * QKV_N];
__device__ __nv_bfloat16 g_qkv_lo[SEQ * QKV_N];
__device__ __nv_bfloat16 g_attn_hi[SEQ * DIM];
__device__ __nv_bfloat16 g_attn_lo[SEQ * DIM];

// ---------------------------------------------------------------------------
// PTX helpers
// ---------------------------------------------------------------------------
__device__ __forceinline__ uint32_t smem_u32(const void* p) {
    uint32_t a;
    asm("{ .reg .u64 t; cvta.to.shared.u64 t, %1; cvt.u32.u64 %0, t; }"
        : "=r"(a) : "l"(p));
    return a;
}

// ldmatrix stays volatile: pins shared-memory read ordering vs barriers.
__device__ __forceinline__ void ldsm_x4(uint32_t* r, uint32_t addr) {
    asm volatile("ldmatrix.sync.aligned.m8n8.x4.shared.b16 {%0,%1,%2,%3}, [%4];"
                 : "=r"(r[0]), "=r"(r[1]), "=r"(r[2]), "=r"(r[3]) : "r"(addr));
}

__device__ __forceinline__ void ldsm_x4_t(uint32_t* r, uint32_t addr) {
    asm volatile("ldmatrix.sync.aligned.m8n8.x4.trans.shared.b16 {%0,%1,%2,%3}, [%4];"
                 : "=r"(r[0]), "=r"(r[1]), "=r"(r[2]), "=r"(r[3]) : "r"(addr));
}

// NON-volatile: pure register op — lets ptxas interleave HMMAs across
// independent accumulators to break latency chains.
__device__ __forceinline__ void mma_bf16(float* d, const uint32_t* a,
                                         const uint32_t* b) {
    asm("mma.sync.aligned.m16n8k16.row.col.f32.bf16.bf16.f32 "
        "{%0,%1,%2,%3}, {%4,%5,%6,%7}, {%8,%9}, {%0,%1,%2,%3};"
        : "+f"(d[0]), "+f"(d[1]), "+f"(d[2]), "+f"(d[3])
        : "r"(a[0]), "r"(a[1]), "r"(a[2]), "r"(a[3]), "r"(b[0]), "r"(b[1]));
}

__device__ __forceinline__ void cp16(uint32_t dst, const void* src) {
    asm volatile("cp.async.cg.shared.global [%0], [%1], 16;"
                 :: "r"(dst), "l"(src));
}
#define CP_COMMIT()   asm volatile("cp.async.commit_group;" ::: "memory")
#define CP_WAIT_1()   asm volatile("cp.async.wait_group 1;" ::: "memory")
#define CP_WAIT_ALL() asm volatile("cp.async.wait_all;" ::: "memory")

// swizzled smem byte offset for (row, 16B-seg), 128B rows (8 segs)
#define SWZ(r, seg) ((uint32_t)((r) * 128 + (((seg) ^ ((r) & 7)) << 4)))
// swizzled smem byte offset for (row, 16B-seg), 64B rows (4 segs)
#define SWZ32(r, seg) ((uint32_t)((r) * 64 + (((seg) ^ (((r) >> 1) & 3)) << 4)))

// pack 2 floats into bf16x2 hi + residual bf16x2 lo
__device__ __forceinline__ void split_pack(float x, float y,
                                           uint32_t& hi, uint32_t& lo) {
    __nv_bfloat162 h = __floats2bfloat162_rn(x, y);
    float2 hf = __bfloat1622float2(h);
    __nv_bfloat162 l = __floats2bfloat162_rn(x - hf.x, y - hf.y);
    hi = *reinterpret_cast<uint32_t*>(&h);
    lo = *reinterpret_cast<uint32_t*>(&l);
}

// ---------------------------------------------------------------------------
// Elementwise split: fp32 -> bf16 hi + bf16 lo
// ---------------------------------------------------------------------------
__global__ __launch_bounds__(256) void split_kernel(
    const float* __restrict__ in,
    __nv_bfloat16* __restrict__ hi, __nv_bfloat16* __restrict__ lo)
{
    int i = (blockIdx.x * 256 + threadIdx.x) * 4;
    float4 v = *(const float4*)(in + i);
    uint32_t h0, l0, h1, l1;
    split_pack(v.x, v.y, h0, l0);
    split_pack(v.z, v.w, h1, l1);
    *(uint32_t*)(hi + i)     = h0;
    *(uint32_t*)(hi + i + 2) = h1;
    *(uint32_t*)(lo + i)     = l0;
    *(uint32_t*)(lo + i + 2) = l1;
}

// ---------------------------------------------------------------------------
// Transpose + split: W[K,N] fp32 -> Wt[N,K] bf16 hi/lo. 32x32 tiles.
// ---------------------------------------------------------------------------
__global__ __launch_bounds__(256) void tsplit_kernel(
    const float* __restrict__ W,
    __nv_bfloat16* __restrict__ hi, __nv_bfloat16* __restrict__ lo,
    int K, int N)
{
    __shared__ float t[32][33];
    const int n0 = blockIdx.x * 32, k0 = blockIdx.y * 32;
    const int tx = threadIdx.x, ty = threadIdx.y;   // 32 x 8

    #pragma unroll
    for (int j = 0; j < 4; j++)
        t[ty + 8 * j][tx] = W[(size_t)(k0 + ty + 8 * j) * N + n0 + tx];
    __syncthreads();

    #pragma unroll
    for (int j = 0; j < 4; j++) {
        int row = ty + 8 * j;
        float v = t[tx][row];
        __nv_bfloat16 h = __float2bfloat16(v);
        size_t o = (size_t)(n0 + row) * K + k0 + tx;
        hi[o] = h;
        lo[o] = __float2bfloat16(v - __bfloat162float(h));
    }
}

// ---------------------------------------------------------------------------
// Split-bf16 tensor-core GEMM via mma.sync (3 terms, fp32 accum).
// BK=32 chunks, 2-stage cp.async pipeline, 2 CTAs/SM.
// ---------------------------------------------------------------------------
#define G_STAGE 32768
#define G_SMEM  (2 * G_STAGE)

__global__ __launch_bounds__(256, 2) void gemm_mma(
    const __nv_bfloat16* __restrict__ Ahi, const __nv_bfloat16* __restrict__ Alo,
    const __nv_bfloat16* __restrict__ Bhi, const __nv_bfloat16* __restrict__ Blo,
    float* __restrict__ C,
    __nv_bfloat16* __restrict__ Chi, __nv_bfloat16* __restrict__ Clo,
    int Mtot, int Ntot, int Ktot,
    const float* __restrict__ bias)
{
    extern __shared__ char smem[];
    const uint32_t sb = smem_u32(smem);
    const int tid  = threadIdx.x;
    const int wid  = tid >> 5;
    const int lane = tid & 31;
    const int row0 = blockIdx.y * 128, col0 = blockIdx.x * 128;

    const int m0 = (wid & 3) * 32;
    const int n0 = (wid >> 2) * 64;

    auto load_chunk = [&](int c, int stg) {
        const uint32_t base = sb + stg * G_STAGE;
        #pragma unroll
        for (int i = 0; i < 8; i++) {
            const int tile = i >> 1;
            int idx = tid + i * 256;
            int r   = (idx >> 2) & 127;
            int seg = idx & 3;
            const __nv_bfloat16* src;
            if (tile == 0)      src = Ahi + (size_t)(row0 + r) * Ktot;
            else if (tile == 1) src = Alo + (size_t)(row0 + r) * Ktot;
            else if (tile == 2) src = Bhi + (size_t)(col0 + r) * Ktot;
            else                src = Blo + (size_t)(col0 + r) * Ktot;
            cp16(base + tile * 8192 + SWZ32(r, seg), src + c * 32 + seg * 8);
        }
    };

    float acc[2][8][4] = {};
    const int nchunks = Ktot >> 5;

    load_chunk(0, 0);
    CP_COMMIT();

    for (int c = 0; c < nchunks; c++) {
        if (c + 1 < nchunks) load_chunk(c + 1, (c + 1) & 1);
        CP_COMMIT();
        CP_WAIT_1();
        __syncthreads();

        const uint32_t st  = sb + (c & 1) * G_STAGE;
        const uint32_t sA  = st;
        const uint32_t sAL = st + 8192;
        const uint32_t sB  = st + 16384;
        const uint32_t sBL = st + 24576;

        #pragma unroll
        for (int ks = 0; ks < 2; ks++) {
            uint32_t aH[2][4], aL[2][4];
            #pragma unroll
            for (int mt = 0; mt < 2; mt++) {
                int r   = m0 + mt * 16 + (lane & 15);
                int seg = ks * 2 + (lane >> 4);
                uint32_t off = SWZ32(r, seg);
                ldsm_x4(aH[mt], sA  + off);
                ldsm_x4(aL[mt], sAL + off);
            }
            #pragma unroll
            for (int np = 0; np < 4; np++) {
                int nr  = n0 + np * 16 + ((lane >> 4) << 3) + (lane & 7);
                int seg = ks * 2 + ((lane >> 3) & 1);
                uint32_t off = SWZ32(nr, seg);
                uint32_t bH[4], bL[4];
                ldsm_x4(bH, sB  + off);
                ldsm_x4(bL, sBL + off);
                #pragma unroll
                for (int mt = 0; mt < 2; mt++) {
                    mma_bf16(acc[mt][np * 2],     aH[mt], bH);
                    mma_bf16(acc[mt][np * 2 + 1], aH[mt], bH + 2);
                    mma_bf16(acc[mt][np * 2],     aH[mt], bL);
                    mma_bf16(acc[mt][np * 2 + 1], aH[mt], bL + 2);
                    mma_bf16(acc[mt][np * 2],     aL[mt], bH);
                    mma_bf16(acc[mt][np * 2 + 1], aL[mt], bH + 2);
                }
            }
        }
        __syncthreads();
    }

    #pragma unroll
    for (int mt = 0; mt < 2; mt++) {
        int r = row0 + m0 + mt * 16 + (lane >> 2);
        #pragma unroll
        for (int nt = 0; nt < 8; nt++) {
            int cc = col0 + n0 + nt * 8 + (lane & 3) * 2;
            float bx = 0.f, by = 0.f;
            if (bias) { bx = bias[cc]; by = bias[cc + 1]; }
            float v0x = acc[mt][nt][0] + bx, v0y = acc[mt][nt][1] + by;
            float v1x = acc[mt][nt][2] + bx, v1y = acc[mt][nt][3] + by;
            if (Chi) {
                uint32_t h0, l0, h1, l1;
                split_pack(v0x, v0y, h0, l0);
                split_pack(v1x, v1y, h1, l1);
                *(uint32_t*)&Chi[(size_t)r * Ntot + cc]       = h0;
                *(uint32_t*)&Clo[(size_t)r * Ntot + cc]       = l0;
                *(uint32_t*)&Chi[(size_t)(r + 8) * Ntot + cc] = h1;
                *(uint32_t*)&Clo[(size_t)(r + 8) * Ntot + cc] = l1;
            } else {
                *(float2*)&C[(size_t)r * Ntot + cc]       = make_float2(v0x, v0y);
                *(float2*)&C[(size_t)(r + 8) * Ntot + cc] = make_float2(v1x, v1y);
            }
        }
    }
}

// ---------------------------------------------------------------------------
// Paired-tile flash attention (causal load balancing).
// Grid (NTILES/2, NHEAD). CTA p handles query tiles t1=p and t2=31-p in one
// kt loop: KV tile loaded once per step, applied to tile2 always and tile1
// while kt<=t1. Every CTA does exactly 33 MMA-steps -> balanced.
// smem 64KB: Q1 hi/lo + Q2 hi/lo (32K) + KV hi/lo (32K). 2 CTAs/SM.
// ---------------------------------------------------------------------------
#define AT_SMEM 65536

__global__ __launch_bounds__(128, 2) void attn_mma(
    const __nv_bfloat16* __restrict__ qkv_hi,
    const __nv_bfloat16* __restrict__ qkv_lo,
    __nv_bfloat16* __restrict__ out_hi,
    __nv_bfloat16* __restrict__ out_lo)
{
    extern __shared__ char smem[];
    const uint32_t sb = smem_u32(smem);
    const uint32_t sQ1h = sb,         sQ1l = sb + 8192;
    const uint32_t sQ2h = sb + 16384, sQ2l = sb + 24576;
    const uint32_t sKh  = sb + 32768, sKl  = sb + 40960;
    const uint32_t sVh  = sb + 49152, sVl  = sb + 57344;

    const int tid = threadIdx.x, wid = tid >> 5, lane = tid & 31;
    const int t1 = blockIdx.x;                 // 0..15
    const int t2 = (NTILES - 1) - t1;          // 31..16
    const int h  = blockIdx.y;
    const int hoff = h * DHEAD;

    // Load both Q tiles
    #pragma unroll
    for (int i = 0; i < 4; i++) {
        int idx = tid + i * 128;
        int r = idx >> 3, seg = idx & 7;
        uint32_t off = SWZ(r, seg);
        size_t g1 = (size_t)(t1 * 64 + r) * QKV_N + hoff + seg * 8;
        size_t g2 = (size_t)(t2 * 64 + r) * QKV_N + hoff + seg * 8;
        cp16(sQ1h + off, qkv_hi + g1);
        cp16(sQ1l + off, qkv_lo + g1);
        cp16(sQ2h + off, qkv_hi + g2);
        cp16(sQ2l + off, qkv_lo + g2);
    }

    float o1[8][4] = {}, o2[8][4] = {};
    float m1[2] = {-1e30f, -1e30f}, l1[2] = {0.f, 0.f};
    float m2[2] = {-1e30f, -1e30f}, l2[2] = {0.f, 0.f};

    const int rloc = wid * 16 + (lane >> 2);   // local row (0..63 within tile)
    const int rA1 = t1 * 64 + rloc;
    const int rA2 = t2 * 64 + rloc;

    // Process one query tile against the currently-loaded KV tile.
    auto process = [&](uint32_t sQh, uint32_t sQl, float (*o)[4],
                       float* m_i, float* l_i, int rA, bool maskit, int k0) {
        // S = Q K^T (3-term split)
        float s[8][4] = {};
        #pragma unroll
        for (int ks = 0; ks < 4; ks++) {
            uint32_t aH[4], aL[4];
            {
                int r   = wid * 16 + (lane & 15);
                int seg = ks * 2 + (lane >> 4);
                ldsm_x4(aH, sQh + SWZ(r, seg));
                ldsm_x4(aL, sQl + SWZ(r, seg));
            }
            #pragma unroll
            for (int np = 0; np < 4; np++) {
                int nr = np * 16 + ((lane >> 4) << 3) + (lane & 7);
                int sg = ks * 2 + ((lane >> 3) & 1);
                uint32_t off = SWZ(nr, sg);
                uint32_t bH[4], bL[4];
                ldsm_x4(bH, sKh + off);
                ldsm_x4(bL, sKl + off);
                mma_bf16(s[np * 2],     aH, bH);
                mma_bf16(s[np * 2 + 1], aH, bH + 2);
                mma_bf16(s[np * 2],     aH, bL);
                mma_bf16(s[np * 2 + 1], aH, bL + 2);
                mma_bf16(s[np * 2],     aL, bH);
                mma_bf16(s[np * 2 + 1], aL, bH + 2);
            }
        }

        // scale + causal mask (diagonal tile only)
        #pragma unroll
        for (int j = 0; j < 8; j++) {
            s[j][0] *= 0.125f; s[j][1] *= 0.125f;
            s[j][2] *= 0.125f; s[j][3] *= 0.125f;
        }
        if (maskit) {
            #pragma unroll
            for (int j = 0; j < 8; j++) {
                int col = k0 + j * 8 + (lane & 3) * 2;
                if (col > rA)         s[j][0] = -1e30f;
                if (col + 1 > rA)     s[j][1] = -1e30f;
                if (col > rA + 8)     s[j][2] = -1e30f;
                if (col + 1 > rA + 8) s[j][3] = -1e30f;
            }
        }

        // online softmax on fragments
        float mxA = -1e30f, mxB = -1e30f;
        #pragma unroll
        for (int j = 0; j < 8; j++) {
            mxA = fmaxf(mxA, fmaxf(s[j][0], s[j][1]));
            mxB = fmaxf(mxB, fmaxf(s[j][2], s[j][3]));
        }
        mxA = fmaxf(mxA, __shfl_xor_sync(0xffffffffu, mxA, 1));
        mxA = fmaxf(mxA, __shfl_xor_sync(0xffffffffu, mxA, 2));
        mxB = fmaxf(mxB, __shfl_xor_sync(0xffffffffu, mxB, 1));
        mxB = fmaxf(mxB, __shfl_xor_sync(0xffffffffu, mxB, 2));

        float mA = fmaxf(m_i[0], mxA), mB = fmaxf(m_i[1], mxB);
        float scA = __expf(m_i[0] - mA), scB = __expf(m_i[1] - mB);
        float lA = 0.f, lB = 0.f;
        #pragma unroll
        for (int j = 0; j < 8; j++) {
            s[j][0] = __expf(s[j][0] - mA);
            s[j][1] = __expf(s[j][1] - mA);
            s[j][2] = __expf(s[j][2] - mB);
            s[j][3] = __expf(s[j][3] - mB);
            lA += s[j][0] + s[j][1];
            lB += s[j][2] + s[j][3];
        }
        lA += __shfl_xor_sync(0xffffffffu, lA, 1);
        lA += __shfl_xor_sync(0xffffffffu, lA, 2);
        lB += __shfl_xor_sync(0xffffffffu, lB, 1);
        lB += __shfl_xor_sync(0xffffffffu, lB, 2);
        l_i[0] = l_i[0] * scA + lA;  m_i[0] = mA;
        l_i[1] = l_i[1] * scB + lB;  m_i[1] = mB;
        #pragma unroll
        for (int j = 0; j < 8; j++) {
            o[j][0] *= scA; o[j][1] *= scA;
            o[j][2] *= scB; o[j][3] *= scB;
        }

        // O += P V (3-term split)
        #pragma unroll
        for (int t = 0; t < 4; t++) {
            uint32_t pH[4], pL[4];
            split_pack(s[2 * t][0],     s[2 * t][1],     pH[0], pL[0]);
            split_pack(s[2 * t][2],     s[2 * t][3],     pH[1], pL[1]);
            split_pack(s[2 * t + 1][0], s[2 * t + 1][1], pH[2], pL[2]);
            split_pack(s[2 * t + 1][2], s[2 * t + 1][3], pH[3], pL[3]);
            #pragma unroll
            for (int sp = 0; sp < 4; sp++) {
                int g  = lane >> 3, rr = lane & 7;
                uint32_t off = SWZ(t * 16 + rr + ((g & 1) << 3),
                                   sp * 2 + (g >> 1));
                uint32_t bH[4], bL[4];
                ldsm_x4_t(bH, sVh + off);
                ldsm_x4_t(bL, sVl + off);
                mma_bf16(o[sp * 2],     pH, bH);
                mma_bf16(o[sp * 2 + 1], pH, bH + 2);
                mma_bf16(o[sp * 2],     pH, bL);
                mma_bf16(o[sp * 2 + 1], pH, bL + 2);
                mma_bf16(o[sp * 2],     pL, bH);
                mma_bf16(o[sp * 2 + 1], pL, bH + 2);
            }
        }
    };

    for (int kt = 0; kt <= t2; kt++) {
        const int k0 = kt * 64;

        #pragma unroll
        for (int i = 0; i < 4; i++) {
            int idx = tid + i * 128;
            int r = idx >> 3, seg = idx & 7;
            size_t g = (size_t)(k0 + r) * QKV_N + DIM + hoff + seg * 8;
            uint32_t off = SWZ(r, seg);
            cp16(sKh + off, qkv_hi + g);
            cp16(sKl + off, qkv_lo + g);
            cp16(sVh + off, qkv_hi + g + DIM);
            cp16(sVl + off, qkv_lo + g + DIM);
        }
        CP_WAIT_ALL();
        __syncthreads();

        process(sQ2h, sQ2l, o2, m2, l2, rA2, kt == t2, k0);
        if (kt <= t1)
            process(sQ1h, sQ1l, o1, m1, l1, rA1, kt == t1, k0);

        __syncthreads();
    }

    // epilogue: normalize, write split bf16 (both tiles)
    {
        float invA = 1.0f / l2[0], invB = 1.0f / l2[1];
        #pragma unroll
        for (int j = 0; j < 8; j++) {
            int d = hoff + j * 8 + (lane & 3) * 2;
            uint32_t hA, lA2, hB, lB2;
            split_pack(o2[j][0] * invA, o2[j][1] * invA, hA, lA2);
            split_pack(o2[j][2] * invB, o2[j][3] * invB, hB, lB2);
            *(uint32_t*)&out_hi[(size_t)rA2 * DIM + d]       = hA;
            *(uint32_t*)&out_lo[(size_t)rA2 * DIM + d]       = lA2;
            *(uint32_t*)&out_hi[(size_t)(rA2 + 8) * DIM + d] = hB;
            *(uint32_t*)&out_lo[(size_t)(rA2 + 8) * DIM + d] = lB2;
        }
    }
    {
        float invA = 1.0f / l1[0], invB = 1.0f / l1[1];
        #pragma unroll
        for (int j = 0; j < 8; j++) {
            int d = hoff + j * 8 + (lane & 3) * 2;
            uint32_t hA, lA2, hB, lB2;
            split_pack(o1[j][0] * invA, o1[j][1] * invA, hA, lA2);
            split_pack(o1[j][2] * invB, o1[j][3] * invB, hB, lB2);
            *(uint32_t*)&out_hi[(size_t)rA1 * DIM + d]       = hA;
            *(uint32_t*)&out_lo[(size_t)rA1 * DIM + d]       = lA2;
            *(uint32_t*)&out_hi[(size_t)(rA1 + 8) * DIM + d] = hB;
            *(uint32_t*)&out_lo[(size_t)(rA1 + 8) * DIM + d] = lB2;
        }
    }
}

// ---------------------------------------------------------------------------
extern "C" void kernel_launch(void* const* d_in, const int* in_sizes, int n_in,
                              void* d_out, int out_size)
{
    const float* x    = (const float*)d_in[0];
    const float* Wqkv = (const float*)d_in[1];
    const float* Wout = (const float*)d_in[2];
    const float* bias = (const float*)d_in[3];
    float* out = (float*)d_out;

    __nv_bfloat16 *xh, *xl, *wqh, *wql, *woh, *wol, *qh, *ql, *ah, *al;
    cudaGetSymbolAddress((void**)&xh,  g_x_hi);
    cudaGetSymbolAddress((void**)&xl,  g_x_lo);
    cudaGetSymbolAddress((void**)&wqh, g_wqkv_hi);
    cudaGetSymbolAddress((void**)&wql, g_wqkv_lo);
    cudaGetSymbolAddress((void**)&woh, g_wout_hi);
    cudaGetSymbolAddress((void**)&wol, g_wout_lo);
    cudaGetSymbolAddress((void**)&qh,  g_qkv_hi);
    cudaGetSymbolAddress((void**)&ql,  g_qkv_lo);
    cudaGetSymbolAddress((void**)&ah,  g_attn_hi);
    cudaGetSymbolAddress((void**)&al,  g_attn_lo);

    cudaFuncSetAttribute(gemm_mma, cudaFuncAttributeMaxDynamicSharedMemorySize,
                         G_SMEM);
    cudaFuncSetAttribute(attn_mma, cudaFuncAttributeMaxDynamicSharedMemorySize,
                         AT_SMEM);

    // Prep: split x, transpose+split weights
    split_kernel<<<SEQ * DIM / 1024, 256>>>(x, xh, xl);
    tsplit_kernel<<<dim3(QKV_N / 32, DIM / 32), dim3(32, 8)>>>(Wqkv, wqh, wql,
                                                               DIM, QKV_N);
    tsplit_kernel<<<dim3(DIM / 32, DIM / 32), dim3(32, 8)>>>(Wout, woh, wol,
                                                             DIM, DIM);

    // 1) qkv = x @ Wqkv  -> bf16 hi/lo directly
    gemm_mma<<<dim3(QKV_N / 128, SEQ / 128), 256, G_SMEM>>>(
        xh, xl, wqh, wql, nullptr, qh, ql, SEQ, QKV_N, DIM, nullptr);

    // 2) attention (paired tiles) -> bf16 hi/lo directly
    attn_mma<<<dim3(NTILES / 2, NHEAD), 128, AT_SMEM>>>(qh, ql, ah, al);

    // 3) out = attn @ Wout + bias  (fp32 output)
    gemm_mma<<<dim3(DIM / 128, SEQ / 128), 256, G_SMEM>>>(
        ah, al, woh, wol, out, nullptr, nullptr, SEQ, DIM, DIM, bias);
}